// round 15
// baseline (speedup 1.0000x reference)
#include <cuda_runtime.h>
#include <cuda_fp16.h>
#include <cstdint>
#include <cstddef>

#define NSEQ  2048
#define CDIM  64
#define CH    512
#define JD    4096
#define BTOT  16
#define ROWS_TOT (BTOT * NSEQ)
#define EPS_F 1e-5f
#define SCALE_F 256.0f          // operand pre-scale (2^8)

// scores stage (k64): A 128x64 fp16 = 16KB, B 128x64 fp16 = 16KB
#define STAGE_BYTES 32768
#define NSTG 3
#define SMEM_DYN (NSTG * STAGE_BYTES)

// ctx/gemm_out stage: A 128x64 fp16 = 16KB, B 64x64 fp16 = 8KB
#define OSTAGE_BYTES 24576
#define OSMEM_DYN (NSTG * OSTAGE_BYTES)

// qkv smem: emb 128x64 (16KB) + 6 W tiles 64x64 (8KB each) = 64KB
#define QSMEM 65536

// ---------------- scratch ----------------
__device__ __half g_embh[(size_t)ROWS_TOT * CDIM];  // emb fp16
__device__ __half g_Ws[(size_t)6 * CH * CDIM];      // Wq h/l, Wk h/l, Wv h/l (x256), [n][k]
__device__ __half g_Qt[(size_t)BTOT * CH * NSEQ];   // [b][i][n], x256
__device__ __half g_Kt[(size_t)BTOT * CH * NSEQ];   // [b][j][n], x256
__device__ __half g_V [(size_t)BTOT * NSEQ * CH];   // [b][n][c], x256
__device__ float  g_S [(size_t)BTOT * CH * JD];     // scores, x2^16
__device__ __half g_A [(size_t)BTOT * CH * JD];     // attn fp16 [b][i][j]
__device__ __half g_CTXh[(size_t)BTOT * NSEQ * CH]; // ctx fp16, true scale
__device__ __half g_Wot[CDIM * CH];                 // Wo^T fp16 [c][k]
__device__ double g_red[BTOT * 2];

// ---------------- helpers ----------------
__device__ __forceinline__ uint32_t smem_u32(const void* p) {
    uint32_t a;
    asm("{ .reg .u64 t; cvta.to.shared.u64 t, %1; cvt.u32.u64 %0, t; }" : "=r"(a) : "l"(p));
    return a;
}
__device__ __forceinline__ void cp_async16(uint32_t s, const void* g) {
    asm volatile("cp.async.cg.shared.global [%0], [%1], 16;" :: "r"(s), "l"(g) : "memory");
}
__device__ __forceinline__ void cp_commit() {
    asm volatile("cp.async.commit_group;" ::: "memory");
}
template <int N>
__device__ __forceinline__ void cp_wait_group() {
    asm volatile("cp.async.wait_group %0;" :: "n"(N) : "memory");
}
// SW128 swizzle for 128-byte rows
__device__ __forceinline__ uint32_t swz(uint32_t off) {
    return off ^ ((off >> 3) & 0x70);
}
__device__ __forceinline__ void mma16816h(float* c, const uint32_t a[4],
                                          uint32_t b0, uint32_t b1) {
    asm volatile(
        "mma.sync.aligned.m16n8k16.row.col.f32.f16.f16.f32 "
        "{%0,%1,%2,%3}, {%4,%5,%6,%7}, {%8,%9}, {%0,%1,%2,%3};"
        : "+f"(c[0]), "+f"(c[1]), "+f"(c[2]), "+f"(c[3])
        : "r"(a[0]), "r"(a[1]), "r"(a[2]), "r"(a[3]), "r"(b0), "r"(b1));
}
__device__ __forceinline__ void ldsm4(uint32_t r[4], uint32_t addr) {
    asm volatile("ldmatrix.sync.aligned.m8n8.x4.shared.b16 {%0,%1,%2,%3}, [%4];"
                 : "=r"(r[0]), "=r"(r[1]), "=r"(r[2]), "=r"(r[3]) : "r"(addr));
}

// load ROWS x 64 fp16 tile (128B rows) into SW128-swizzled smem (256 threads)
template <int ROWS>
__device__ __forceinline__ void ldtile(uint32_t sdst, const char* g, size_t stride, int tid) {
#pragma unroll
    for (int t = 0; t < ROWS / 32; t++) {
        int op = tid + t * 256;
        int row = op >> 3, c = op & 7;
        uint32_t off = row * 128 + c * 16;
        cp_async16(sdst + swz(off), g + (size_t)row * stride + c * 16);
    }
}

// ============================================================================
// scores compute: warp tile 64x32 (4 mt x 2 np); one k64 stage
// ============================================================================
__device__ __forceinline__ void compute_stage(uint32_t sA, uint32_t sB,
                                              const uint32_t baseA[4],
                                              const uint32_t baseB[2],
                                              float acc[4][4][4]) {
#pragma unroll
    for (int kk = 0; kk < 4; kk++) {
        uint32_t kb = kk * 32;
        uint32_t ah[4][4], bf[2][4];
#pragma unroll
        for (int mt = 0; mt < 4; mt++)
            ldsm4(ah[mt], sA + (baseA[mt] ^ kb));
#pragma unroll
        for (int np = 0; np < 2; np++)
            ldsm4(bf[np], sB + (baseB[np] ^ kb));
#pragma unroll
        for (int np = 0; np < 2; np++) {
#pragma unroll
            for (int h = 0; h < 2; h++) {
                uint32_t b0 = bf[np][h], b1 = bf[np][2 + h];
                int nt = np * 2 + h;
#pragma unroll
                for (int mt = 0; mt < 4; mt++)
                    mma16816h(acc[mt][nt], ah[mt], b0, b1);
            }
        }
    }
}

// ctx/gemm_out compute: warp tile 32x32 (2 mt x 2 np); one k64 stage
__device__ __forceinline__ void compute_stage2(uint32_t sA, uint32_t sB,
                                               const uint32_t baseA[2],
                                               const uint32_t baseB[2],
                                               float acc[2][4][4]) {
#pragma unroll
    for (int kk = 0; kk < 4; kk++) {
        uint32_t kb = kk * 32;
        uint32_t ah[2][4], bf[2][4];
#pragma unroll
        for (int mt = 0; mt < 2; mt++)
            ldsm4(ah[mt], sA + (baseA[mt] ^ kb));
#pragma unroll
        for (int np = 0; np < 2; np++)
            ldsm4(bf[np], sB + (baseB[np] ^ kb));
#pragma unroll
        for (int np = 0; np < 2; np++) {
#pragma unroll
            for (int h = 0; h < 2; h++) {
                uint32_t b0 = bf[np][h], b1 = bf[np][2 + h];
                int nt = np * 2 + h;
#pragma unroll
                for (int mt = 0; mt < 2; mt++)
                    mma16816h(acc[mt][nt], ah[mt], b0, b1);
            }
        }
    }
}

// ============================================================================
// scores: S[ob][i][j] = sum_n Qt[ob][i][n] * Kt[kvb][jc][n]   (x 2^16)
// CTA tile 128(i) x 128(j), grid (32, 4, 16), block 256, 2 CTAs/SM
// ============================================================================
__global__ void __launch_bounds__(256, 2) scores_mma() {
    extern __shared__ char dsm[];
    uint32_t sb = smem_u32(dsm);
    __shared__ double sred[8], sred2[8];

    int ob = blockIdx.z;
    int kvbase = (ob < 8) ? 8 : 0;
    int i0 = blockIdx.y << 7;
    int j0 = blockIdx.x << 7;
    int kvb = kvbase + (j0 >> 9);
    int jc0 = j0 & 511;

    int tid = threadIdx.x;
    int wid = tid >> 5, lane = tid & 31;
    int g = lane >> 2, tg = lane & 3;
    int wm = (wid & 1) * 64, wn = (wid >> 1) * 32;

    uint32_t baseA[4], baseB[2];
    uint32_t lrow = lane & 15, lcol = (lane >> 4) * 16;
#pragma unroll
    for (int mt = 0; mt < 4; mt++) baseA[mt] = swz((wm + mt * 16 + lrow) * 128 + lcol);
#pragma unroll
    for (int np = 0; np < 2; np++) baseB[np] = swz((wn + np * 16 + lrow) * 128 + lcol);

    const char* AB = (const char*)g_Qt + ((size_t)ob * CH + i0) * NSEQ * 2;
    const char* BB = (const char*)g_Kt + ((size_t)kvb * CH + jc0) * NSEQ * 2;
    const size_t st = NSEQ * 2;

    float acc[4][4][4];
#pragma unroll
    for (int a = 0; a < 4; a++)
#pragma unroll
        for (int b = 0; b < 4; b++)
#pragma unroll
            for (int c = 0; c < 4; c++) acc[a][b][c] = 0.f;

    const int NCH = NSEQ / 64;   // 32

    auto load_chunk = [&](int c, int stg) {
        uint32_t s = sb + stg * STAGE_BYTES;
        size_t ko = (size_t)c * 128;
        ldtile<128>(s,         AB + ko, st, tid);
        ldtile<128>(s + 16384, BB + ko, st, tid);
        cp_commit();
    };

    load_chunk(0, 0);
    load_chunk(1, 1);
    for (int c = 0; c < NCH; c++) {
        if (c + 1 < NCH) cp_wait_group<1>(); else cp_wait_group<0>();
        __syncthreads();
        if (c + 2 < NCH) load_chunk(c + 2, (c + 2) % NSTG);
        uint32_t s = sb + (c % NSTG) * STAGE_BYTES;
        compute_stage(s, s + 16384, baseA, baseB, acc);
    }

    float* gout = g_S + (size_t)ob * CH * JD;
    float s1 = 0.f, s2 = 0.f;
#pragma unroll
    for (int mt = 0; mt < 4; mt++) {
#pragma unroll
        for (int nt = 0; nt < 4; nt++) {
            int row = i0 + wm + mt * 16 + g;
            int col = j0 + wn + nt * 8 + tg * 2;
            float v0 = acc[mt][nt][0], v1 = acc[mt][nt][1];
            float v2 = acc[mt][nt][2], v3 = acc[mt][nt][3];
            *(float2*)&gout[(size_t)row * JD + col] = make_float2(v0, v1);
            *(float2*)&gout[(size_t)(row + 8) * JD + col] = make_float2(v2, v3);
            s1 += v0 + v1 + v2 + v3;
            s2 += v0 * v0 + v1 * v1 + v2 * v2 + v3 * v3;
        }
    }
    double d1 = (double)s1, d2 = (double)s2;
    for (int off = 16; off > 0; off >>= 1) {
        d1 += __shfl_down_sync(0xffffffffu, d1, off);
        d2 += __shfl_down_sync(0xffffffffu, d2, off);
    }
    if (lane == 0) { sred[wid] = d1; sred2[wid] = d2; }
    __syncthreads();
    if (tid == 0) {
        double t1 = 0.0, t2 = 0.0;
#pragma unroll
        for (int w = 0; w < 8; w++) { t1 += sred[w]; t2 += sred2[w]; }
        atomicAdd(&g_red[2 * ob], t1);
        atomicAdd(&g_red[2 * ob + 1], t2);
    }
}

// ============================================================================
// ctx: CTX[ob][n][i] = sum_j V[kvb(j)][n][jc] * attn[ob][i][j]
// CTA tile 128(n) x 64(i), grid (CH/64=8, NSEQ/128=16, 16) = 2048 blocks,
// block 256 (8 warps of 32x32), 2 CTAs/SM. Finer blocks kill wave tail.
// ============================================================================
__global__ void __launch_bounds__(256, 2) ctx_mma() {
    extern __shared__ char dsm[];
    uint32_t sb = smem_u32(dsm);

    int ob = blockIdx.z;
    int kvbase = (ob < 8) ? 8 : 0;
    int i0 = blockIdx.x << 6;
    int n0 = blockIdx.y << 7;

    int tid = threadIdx.x;
    int wid = tid >> 5, lane = tid & 31;
    int g = lane >> 2, tg = lane & 3;
    int wm = (wid & 3) * 32, wn = (wid >> 2) * 32;

    uint32_t baseA[2], baseB[2];
    uint32_t lrow = lane & 15, lcol = (lane >> 4) * 16;
#pragma unroll
    for (int mt = 0; mt < 2; mt++) baseA[mt] = swz((wm + mt * 16 + lrow) * 128 + lcol);
#pragma unroll
    for (int np = 0; np < 2; np++) baseB[np] = swz((wn + np * 16 + lrow) * 128 + lcol);

    const char* BB = (const char*)g_A + ((size_t)ob * CH + i0) * JD * 2;

    float acc[2][4][4];
#pragma unroll
    for (int a = 0; a < 2; a++)
#pragma unroll
        for (int b = 0; b < 4; b++)
#pragma unroll
            for (int c = 0; c < 4; c++) acc[a][b][c] = 0.f;

    const int NCH = JD / 64;   // 64

    auto load_chunk = [&](int c, int stg) {
        uint32_t s = sb + stg * OSTAGE_BYTES;
        int j0c = c * 64;
        int kvb = kvbase + (j0c >> 9);
        int jc0 = j0c & 511;
        const char* Ap = (const char*)g_V + (((size_t)kvb * NSEQ + n0) * CH + jc0) * 2;
        ldtile<128>(s,        Ap, CH * 2, tid);
        ldtile<64>(s + 16384, BB + (size_t)j0c * 2, JD * 2, tid);
        cp_commit();
    };

    load_chunk(0, 0);
    load_chunk(1, 1);
    for (int c = 0; c < NCH; c++) {
        if (c + 1 < NCH) cp_wait_group<1>(); else cp_wait_group<0>();
        __syncthreads();
        if (c + 2 < NCH) load_chunk(c + 2, (c + 2) % NSTG);
        uint32_t s = sb + (c % NSTG) * OSTAGE_BYTES;
        compute_stage2(s, s + 16384, baseA, baseB, acc);
    }

    const float ds = 1.0f / SCALE_F;   // undo V pre-scale
    __half* gout = g_CTXh + (size_t)ob * NSEQ * CH;
#pragma unroll
    for (int mt = 0; mt < 2; mt++) {
#pragma unroll
        for (int nt = 0; nt < 4; nt++) {
            int row = n0 + wm + mt * 16 + g;
            int col = i0 + wn + nt * 8 + tg * 2;
            *(__half2*)&gout[(size_t)row * CH + col] =
                __floats2half2_rn(acc[mt][nt][0] * ds, acc[mt][nt][1] * ds);
            *(__half2*)&gout[(size_t)(row + 8) * CH + col] =
                __floats2half2_rn(acc[mt][nt][2] * ds, acc[mt][nt][3] * ds);
        }
    }
}

// ============================================================================
// fused prep: blocks [0,2048) emb->fp16; [2048,2432) W q/k/v split x256;
// [2432,2560) Wo^T fp16. Block 0 also zeroes g_red.
// ============================================================================
__global__ void __launch_bounds__(256) prep_all(const float* __restrict__ emb,
                                                const float* __restrict__ Wq,
                                                const float* __restrict__ Wk,
                                                const float* __restrict__ Wv,
                                                const float* __restrict__ Wo) {
    int bx = blockIdx.x;
    int tid = threadIdx.x;
    if (bx < 2048) {
        if (bx == 0 && tid < BTOT * 2) g_red[tid] = 0.0;
        size_t idx = ((size_t)bx * 256 + tid) * 4;
        float4 v = *(const float4*)&emb[idx];
        union { __half h[4]; uint2 u; } p;
        p.h[0] = __float2half(v.x); p.h[1] = __float2half(v.y);
        p.h[2] = __float2half(v.z); p.h[3] = __float2half(v.w);
        *(uint2*)&g_embh[idx] = p.u;
    } else if (bx < 2432) {
        int r = bx - 2048;
        int w = r >> 7;                       // 0..2
        int idx = (r & 127) * 256 + tid;      // 0..32767
        const float* src = (w == 0) ? Wq : (w == 1) ? Wk : Wv;
        int n = idx >> 6, k = idx & 63;
        float v = src[(size_t)k * CH + n] * SCALE_F;
        __half h = __float2half(v);
        __half l = __float2half(v - __half2float(h));
        size_t base = (size_t)(2 * w) * CH * CDIM;
        g_Ws[base + (size_t)n * CDIM + k] = h;
        g_Ws[base + CH * CDIM + (size_t)n * CDIM + k] = l;
    } else {
        int idx = (bx - 2432) * 256 + tid;    // 0..32767
        int k = idx >> 6, n = idx & 63;
        g_Wot[n * CH + k] = __float2half(Wo[(size_t)k * CDIM + n]);
    }
}

// ============================================================================
// QKV via tensor cores: Qt/Kt/V = embh @ Wsplit (x256).
// CTA tile 128(m) x 64(n), 8 warps 32x32, grid (CH/64=8, ROWS_TOT/128=256).
// ============================================================================
__global__ void __launch_bounds__(256) qkv_mma() {
    extern __shared__ char dsm[];
    uint32_t sb = smem_u32(dsm);
    uint32_t sEmb = sb;

    int bn = blockIdx.x << 6;
    int bm = blockIdx.y << 7;
    int tid = threadIdx.x;
    int wid = tid >> 5, lane = tid & 31;
    int g = lane >> 2, tg = lane & 3;
    int wm = (wid & 3) * 32, wn = (wid >> 2) * 32;

    uint32_t baseA[2], baseB[2];
    uint32_t lrow = lane & 15, lcol = (lane >> 4) * 16;
#pragma unroll
    for (int mt = 0; mt < 2; mt++) baseA[mt] = swz((wm + mt * 16 + lrow) * 128 + lcol);
#pragma unroll
    for (int np = 0; np < 2; np++) baseB[np] = swz((wn + np * 16 + lrow) * 128 + lcol);

    ldtile<128>(sEmb, (const char*)g_embh + (size_t)bm * CDIM * 2, CDIM * 2, tid);
#pragma unroll
    for (int w6 = 0; w6 < 6; w6++) {
        const char* wp = (const char*)g_Ws + ((size_t)w6 * CH + bn) * CDIM * 2;
        ldtile<64>(sb + 16384 + w6 * 8192, wp, CDIM * 2, tid);
    }
    cp_commit();
    cp_wait_group<0>();
    __syncthreads();

    float acc[3][2][4][4];
#pragma unroll
    for (int w = 0; w < 3; w++)
#pragma unroll
        for (int a = 0; a < 2; a++)
#pragma unroll
            for (int b = 0; b < 4; b++)
#pragma unroll
                for (int c = 0; c < 4; c++) acc[w][a][b][c] = 0.f;

#pragma unroll
    for (int kk = 0; kk < 4; kk++) {
        uint32_t kb = kk * 32;
        uint32_t ah[2][4];
#pragma unroll
        for (int mt = 0; mt < 2; mt++)
            ldsm4(ah[mt], sEmb + (baseA[mt] ^ kb));
#pragma unroll
        for (int w = 0; w < 3; w++) {
            uint32_t sH = sb + 16384 + (2 * w) * 8192;
            uint32_t sL = sH + 8192;
            uint32_t bh[2][4], bl[2][4];
#pragma unroll
            for (int np = 0; np < 2; np++) {
                ldsm4(bh[np], sH + (baseB[np] ^ kb));
                ldsm4(bl[np], sL + (baseB[np] ^ kb));
            }
#pragma unroll
            for (int np = 0; np < 2; np++) {
#pragma unroll
                for (int h = 0; h < 2; h++) {
                    int nt = np * 2 + h;
#pragma unroll
                    for (int mt = 0; mt < 2; mt++) {
                        mma16816h(acc[w][mt][nt], ah[mt], bh[np][h], bh[np][2 + h]);
                        mma16816h(acc[w][mt][nt], ah[mt], bl[np][h], bl[np][2 + h]);
                    }
                }
            }
        }
    }

    // V direct (row-major [m][c])
#pragma unroll
    for (int mt = 0; mt < 2; mt++) {
#pragma unroll
        for (int nt = 0; nt < 4; nt++) {
            int row = bm + wm + mt * 16 + g;
            int col = bn + wn + nt * 8 + tg * 2;
            *(__half2*)&g_V[(size_t)row * CH + col] =
                __floats2half2_rn(acc[2][mt][nt][0], acc[2][mt][nt][1]);
            *(__half2*)&g_V[(size_t)(row + 8) * CH + col] =
                __floats2half2_rn(acc[2][mt][nt][2], acc[2][mt][nt][3]);
        }
    }

    // Qt / Kt transposed via smem stage (pitch 136 halves)
    __half* stT = (__half*)dsm;
    int b = bm >> 11;
    int nloc = bm & 2047;
#pragma unroll
    for (int w = 0; w < 2; w++) {
        __syncthreads();
#pragma unroll
        for (int mt = 0; mt < 2; mt++) {
#pragma unroll
            for (int nt = 0; nt < 4; nt++) {
                int m = wm + mt * 16 + g;
                int col = wn + nt * 8 + tg * 2;
                stT[(col + 0) * 136 + m]     = __float2half(acc[w][mt][nt][0]);
                stT[(col + 1) * 136 + m]     = __float2half(acc[w][mt][nt][1]);
                stT[(col + 0) * 136 + m + 8] = __float2half(acc[w][mt][nt][2]);
                stT[(col + 1) * 136 + m + 8] = __float2half(acc[w][mt][nt][3]);
            }
        }
        __syncthreads();
        __half* dst = ((w == 0) ? g_Qt : g_Kt) +
                      (size_t)b * CH * NSEQ + (size_t)bn * NSEQ + nloc;
#pragma unroll
        for (int k = 0; k < 4; k++) {
            int idx = tid + k * 256;
            int row = idx >> 4, c8 = (idx & 15) * 8;
            *(uint4*)&dst[(size_t)row * NSEQ + c8] = *(uint4*)&stT[row * 136 + c8];
        }
    }
}

// ============================================================================
// out projection via tensor cores: OUT[M,64] = CTXh[M,512] @ Wot^T
// ============================================================================
__global__ void __launch_bounds__(256, 2) gemm_out_mma(float* __restrict__ Cm) {
    extern __shared__ char dsm[];
    uint32_t sb = smem_u32(dsm);

    int bm = blockIdx.x << 7;
    int tid = threadIdx.x;
    int wid = tid >> 5, lane = tid & 31;
    int g = lane >> 2, tg = lane & 3;
    int wm = (wid & 3) * 32, wn = (wid >> 2) * 32;

    uint32_t baseA[2], baseB[2];
    uint32_t lrow = lane & 15, lcol = (lane >> 4) * 16;
#pragma unroll
    for (int mt = 0; mt < 2; mt++) baseA[mt] = swz((wm + mt * 16 + lrow) * 128 + lcol);
#pragma unroll
    for (int np = 0; np < 2; np++) baseB[np] = swz((wn + np * 16 + lrow) * 128 + lcol);

    const char* AB = (const char*)g_CTXh + (size_t)bm * CH * 2;
    const char* BB = (const char*)g_Wot;

    float acc[2][4][4];
#pragma unroll
    for (int a = 0; a < 2; a++)
#pragma unroll
        for (int b = 0; b < 4; b++)
#pragma unroll
            for (int c = 0; c < 4; c++) acc[a][b][c] = 0.f;

    const int NCH = CH / 64;   // 8

    auto load_chunk = [&](int c, int stg) {
        uint32_t s = sb + stg * OSTAGE_BYTES;
        size_t ko = (size_t)c * 128;
        ldtile<128>(s,         AB + ko, CH * 2, tid);
        ldtile<64>(s + 16384,  BB + ko, CH * 2, tid);
        cp_commit();
    };

    load_chunk(0, 0);
    load_chunk(1, 1);
    for (int c = 0; c < NCH; c++) {
        if (c + 1 < NCH) cp_wait_group<1>(); else cp_wait_group<0>();
        __syncthreads();
        if (c + 2 < NCH) load_chunk(c + 2, (c + 2) % NSTG);
        uint32_t s = sb + (c % NSTG) * OSTAGE_BYTES;
        compute_stage2(s, s + 16384, baseA, baseB, acc);
    }

#pragma unroll
    for (int mt = 0; mt < 2; mt++) {
#pragma unroll
        for (int nt = 0; nt < 4; nt++) {
            int row = bm + wm + mt * 16 + g;
            int col = wn + nt * 8 + tg * 2;
            *(float2*)&Cm[(size_t)row * CDIM + col] =
                make_float2(acc[mt][nt][0], acc[mt][nt][1]);
            *(float2*)&Cm[(size_t)(row + 8) * CDIM + col] =
                make_float2(acc[mt][nt][2], acc[mt][nt][3]);
        }
    }
}

// ============================================================================
// softmax (fused rstd finalize): scale + softmax over j, write attn fp16.
// ============================================================================
__global__ void __launch_bounds__(256) softmax_k() {
    int row = blockIdx.x;
    int b = row >> 9;
    __shared__ float srstd;
    __shared__ float red[8];
    int t = threadIdx.x;

    if (t == 0) {
        const double SC = 65536.0;
        double n = (double)CH * (double)JD;
        double mean = g_red[2 * b] / (n * SC);
        double var  = g_red[2 * b + 1] / (n * SC * SC) - mean * mean;
        srstd = rsqrtf((float)var + EPS_F) / (float)SC;
    }

    const float* p = g_S + (size_t)row * JD;
    float4 xv[4];
#pragma unroll
    for (int u = 0; u < 4; u++)
        xv[u] = *(const float4*)&p[u * 1024 + t * 4];
    __syncthreads();
    float rstd = srstd;

    float* x = (float*)xv;
    float mx = -1e30f;
#pragma unroll
    for (int u = 0; u < 16; u++) {
        x[u] *= rstd;
        mx = fmaxf(mx, x[u]);
    }
    for (int off = 16; off > 0; off >>= 1)
        mx = fmaxf(mx, __shfl_xor_sync(0xffffffffu, mx, off));
    int lane = t & 31, wid = t >> 5;
    if (lane == 0) red[wid] = mx;
    __syncthreads();
    float gm = red[0];
#pragma unroll
    for (int w = 1; w < 8; w++) gm = fmaxf(gm, red[w]);
    __syncthreads();

    float sum = 0.f;
#pragma unroll
    for (int u = 0; u < 16; u++) {
        x[u] = __expf(x[u] - gm);
        sum += x[u];
    }
    for (int off = 16; off > 0; off >>= 1)
        sum += __shfl_xor_sync(0xffffffffu, sum, off);
    if (lane == 0) red[wid] = sum;
    __syncthreads();
    float tot = 0.f;
#pragma unroll
    for (int w = 0; w < 8; w++) tot += red[w];
    float inv = 1.0f / tot;

    __half* ah = g_A + (size_t)row * JD;
#pragma unroll
    for (int u = 0; u < 4; u++) {
        union { __half v[4]; uint2 q; } pk;
#pragma unroll
        for (int e = 0; e < 4; e++)
            pk.v[e] = __float2half(x[u * 4 + e] * inv);
        *(uint2*)&ah[u * 1024 + t * 4] = pk.q;
    }
}

// ============================================================================
// launch
// ============================================================================
extern "C" void kernel_launch(void* const* d_in, const int* in_sizes, int n_in,
                              void* d_out, int out_size) {
    const float* emb = (const float*)d_in[0];
    const float* Wq  = (const float*)d_in[1];
    const float* Wk  = (const float*)d_in[2];
    const float* Wv  = (const float*)d_in[3];
    const float* Wo  = (const float*)d_in[4];
    float* outp = (float*)d_out;

    cudaFuncSetAttribute(scores_mma, cudaFuncAttributeMaxDynamicSharedMemorySize, SMEM_DYN);
    cudaFuncSetAttribute(ctx_mma, cudaFuncAttributeMaxDynamicSharedMemorySize, OSMEM_DYN);
    cudaFuncSetAttribute(gemm_out_mma, cudaFuncAttributeMaxDynamicSharedMemorySize, OSMEM_DYN);
    cudaFuncSetAttribute(qkv_mma, cudaFuncAttributeMaxDynamicSharedMemorySize, QSMEM);

    prep_all<<<2560, 256>>>(emb, Wq, Wk, Wv, Wo);

    qkv_mma<<<dim3(CH / 64, ROWS_TOT / 128), 256, QSMEM>>>();

    scores_mma<<<dim3(JD / 128, CH / 128, BTOT), 256, SMEM_DYN>>>();

    softmax_k<<<BTOT * CH, 256>>>();

    ctx_mma<<<dim3(CH / 64, NSEQ / 128, BTOT), 256, OSMEM_DYN>>>();

    gemm_out_mma<<<ROWS_TOT / 128, 256, OSMEM_DYN>>>(outp);
}

// round 16
// speedup vs baseline: 1.0437x; 1.0437x over previous
#include <cuda_runtime.h>
#include <cuda_fp16.h>
#include <cstdint>
#include <cstddef>

#define NSEQ  2048
#define CDIM  64
#define CH    512
#define JD    4096
#define BTOT  16
#define ROWS_TOT (BTOT * NSEQ)
#define EPS_F 1e-5f
#define SCALE_F 256.0f          // operand pre-scale (2^8)

// scores/ctx stage (k64): A 128x64 fp16 = 16KB, B 128x64 fp16 = 16KB
#define STAGE_BYTES 32768
#define NSTG 3
#define SMEM_DYN (NSTG * STAGE_BYTES)

// gemm_out stage: A 128x64 fp16 = 16KB, B 64x64 fp16 = 8KB
#define OSTAGE_BYTES 24576
#define OSMEM_DYN (NSTG * OSTAGE_BYTES)

// qkv smem: emb 128x64 (16KB) + 6 W tiles 64x64 (8KB each) = 64KB
#define QSMEM 65536

// ---------------- scratch ----------------
__device__ __half g_embh[(size_t)ROWS_TOT * CDIM];  // emb fp16
__device__ __half g_Ws[(size_t)6 * CH * CDIM];      // Wq h/l, Wk h/l, Wv h/l (x256), [n][k]
__device__ __half g_Qt[(size_t)BTOT * CH * NSEQ];   // [b][i][n], x256
__device__ __half g_Kt[(size_t)BTOT * CH * NSEQ];   // [b][j][n], x256
__device__ __half g_V [(size_t)BTOT * NSEQ * CH];   // [b][n][c], x256
__device__ float  g_S [(size_t)BTOT * CH * JD];     // scores, x2^16
__device__ __half g_A [(size_t)BTOT * CH * JD];     // attn fp16 [b][i][j]
__device__ __half g_CTXh[(size_t)BTOT * NSEQ * CH]; // ctx fp16, true scale
__device__ __half g_Wot[CDIM * CH];                 // Wo^T fp16 [c][k]
__device__ double g_red[BTOT * 2];

// ---------------- helpers ----------------
__device__ __forceinline__ uint32_t smem_u32(const void* p) {
    uint32_t a;
    asm("{ .reg .u64 t; cvta.to.shared.u64 t, %1; cvt.u32.u64 %0, t; }" : "=r"(a) : "l"(p));
    return a;
}
__device__ __forceinline__ void cp_async16(uint32_t s, const void* g) {
    asm volatile("cp.async.cg.shared.global [%0], [%1], 16;" :: "r"(s), "l"(g) : "memory");
}
__device__ __forceinline__ void cp_commit() {
    asm volatile("cp.async.commit_group;" ::: "memory");
}
template <int N>
__device__ __forceinline__ void cp_wait_group() {
    asm volatile("cp.async.wait_group %0;" :: "n"(N) : "memory");
}
// SW128 swizzle for 128-byte rows
__device__ __forceinline__ uint32_t swz(uint32_t off) {
    return off ^ ((off >> 3) & 0x70);
}
__device__ __forceinline__ void mma16816h(float* c, const uint32_t a[4],
                                          uint32_t b0, uint32_t b1) {
    asm volatile(
        "mma.sync.aligned.m16n8k16.row.col.f32.f16.f16.f32 "
        "{%0,%1,%2,%3}, {%4,%5,%6,%7}, {%8,%9}, {%0,%1,%2,%3};"
        : "+f"(c[0]), "+f"(c[1]), "+f"(c[2]), "+f"(c[3])
        : "r"(a[0]), "r"(a[1]), "r"(a[2]), "r"(a[3]), "r"(b0), "r"(b1));
}
__device__ __forceinline__ void ldsm4(uint32_t r[4], uint32_t addr) {
    asm volatile("ldmatrix.sync.aligned.m8n8.x4.shared.b16 {%0,%1,%2,%3}, [%4];"
                 : "=r"(r[0]), "=r"(r[1]), "=r"(r[2]), "=r"(r[3]) : "r"(addr));
}

// load ROWS x 64 fp16 tile (128B rows) into SW128-swizzled smem (256 threads)
template <int ROWS>
__device__ __forceinline__ void ldtile(uint32_t sdst, const char* g, size_t stride, int tid) {
#pragma unroll
    for (int t = 0; t < ROWS / 32; t++) {
        int op = tid + t * 256;
        int row = op >> 3, c = op & 7;
        uint32_t off = row * 128 + c * 16;
        cp_async16(sdst + swz(off), g + (size_t)row * stride + c * 16);
    }
}

// ============================================================================
// scores/ctx compute: warp tile 64x32 (4 mt x 2 np); one k64 stage
// ============================================================================
__device__ __forceinline__ void compute_stage(uint32_t sA, uint32_t sB,
                                              const uint32_t baseA[4],
                                              const uint32_t baseB[2],
                                              float acc[4][4][4]) {
#pragma unroll
    for (int kk = 0; kk < 4; kk++) {
        uint32_t kb = kk * 32;
        uint32_t ah[4][4], bf[2][4];
#pragma unroll
        for (int mt = 0; mt < 4; mt++)
            ldsm4(ah[mt], sA + (baseA[mt] ^ kb));
#pragma unroll
        for (int np = 0; np < 2; np++)
            ldsm4(bf[np], sB + (baseB[np] ^ kb));
#pragma unroll
        for (int np = 0; np < 2; np++) {
#pragma unroll
            for (int h = 0; h < 2; h++) {
                uint32_t b0 = bf[np][h], b1 = bf[np][2 + h];
                int nt = np * 2 + h;
#pragma unroll
                for (int mt = 0; mt < 4; mt++)
                    mma16816h(acc[mt][nt], ah[mt], b0, b1);
            }
        }
    }
}

// gemm_out compute: warp tile 32x32 (2 mt x 2 np); one k64 stage
__device__ __forceinline__ void compute_stage2(uint32_t sA, uint32_t sB,
                                               const uint32_t baseA[2],
                                               const uint32_t baseB[2],
                                               float acc[2][4][4]) {
#pragma unroll
    for (int kk = 0; kk < 4; kk++) {
        uint32_t kb = kk * 32;
        uint32_t ah[2][4], bf[2][4];
#pragma unroll
        for (int mt = 0; mt < 2; mt++)
            ldsm4(ah[mt], sA + (baseA[mt] ^ kb));
#pragma unroll
        for (int np = 0; np < 2; np++)
            ldsm4(bf[np], sB + (baseB[np] ^ kb));
#pragma unroll
        for (int np = 0; np < 2; np++) {
#pragma unroll
            for (int h = 0; h < 2; h++) {
                uint32_t b0 = bf[np][h], b1 = bf[np][2 + h];
                int nt = np * 2 + h;
#pragma unroll
                for (int mt = 0; mt < 2; mt++)
                    mma16816h(acc[mt][nt], ah[mt], b0, b1);
            }
        }
    }
}

// ============================================================================
// scores: S[ob][i][j] = sum_n Qt[ob][i][n] * Kt[kvb][jc][n]   (x 2^16)
// CTA tile 128(i) x 128(j), grid (32, 4, 16), block 256, 2 CTAs/SM
// ============================================================================
__global__ void __launch_bounds__(256, 2) scores_mma() {
    extern __shared__ char dsm[];
    uint32_t sb = smem_u32(dsm);
    __shared__ double sred[8], sred2[8];

    int ob = blockIdx.z;
    int kvbase = (ob < 8) ? 8 : 0;
    int i0 = blockIdx.y << 7;
    int j0 = blockIdx.x << 7;
    int kvb = kvbase + (j0 >> 9);
    int jc0 = j0 & 511;

    int tid = threadIdx.x;
    int wid = tid >> 5, lane = tid & 31;
    int g = lane >> 2, tg = lane & 3;
    int wm = (wid & 1) * 64, wn = (wid >> 1) * 32;

    uint32_t baseA[4], baseB[2];
    uint32_t lrow = lane & 15, lcol = (lane >> 4) * 16;
#pragma unroll
    for (int mt = 0; mt < 4; mt++) baseA[mt] = swz((wm + mt * 16 + lrow) * 128 + lcol);
#pragma unroll
    for (int np = 0; np < 2; np++) baseB[np] = swz((wn + np * 16 + lrow) * 128 + lcol);

    const char* AB = (const char*)g_Qt + ((size_t)ob * CH + i0) * NSEQ * 2;
    const char* BB = (const char*)g_Kt + ((size_t)kvb * CH + jc0) * NSEQ * 2;
    const size_t st = NSEQ * 2;

    float acc[4][4][4];
#pragma unroll
    for (int a = 0; a < 4; a++)
#pragma unroll
        for (int b = 0; b < 4; b++)
#pragma unroll
            for (int c = 0; c < 4; c++) acc[a][b][c] = 0.f;

    const int NCH = NSEQ / 64;   // 32

    auto load_chunk = [&](int c, int stg) {
        uint32_t s = sb + stg * STAGE_BYTES;
        size_t ko = (size_t)c * 128;
        ldtile<128>(s,         AB + ko, st, tid);
        ldtile<128>(s + 16384, BB + ko, st, tid);
        cp_commit();
    };

    load_chunk(0, 0);
    load_chunk(1, 1);
    for (int c = 0; c < NCH; c++) {
        if (c + 1 < NCH) cp_wait_group<1>(); else cp_wait_group<0>();
        __syncthreads();
        if (c + 2 < NCH) load_chunk(c + 2, (c + 2) % NSTG);
        uint32_t s = sb + (c % NSTG) * STAGE_BYTES;
        compute_stage(s, s + 16384, baseA, baseB, acc);
    }

    float* gout = g_S + (size_t)ob * CH * JD;
    float s1 = 0.f, s2 = 0.f;
#pragma unroll
    for (int mt = 0; mt < 4; mt++) {
#pragma unroll
        for (int nt = 0; nt < 4; nt++) {
            int row = i0 + wm + mt * 16 + g;
            int col = j0 + wn + nt * 8 + tg * 2;
            float v0 = acc[mt][nt][0], v1 = acc[mt][nt][1];
            float v2 = acc[mt][nt][2], v3 = acc[mt][nt][3];
            *(float2*)&gout[(size_t)row * JD + col] = make_float2(v0, v1);
            *(float2*)&gout[(size_t)(row + 8) * JD + col] = make_float2(v2, v3);
            s1 += v0 + v1 + v2 + v3;
            s2 += v0 * v0 + v1 * v1 + v2 * v2 + v3 * v3;
        }
    }
    double d1 = (double)s1, d2 = (double)s2;
    for (int off = 16; off > 0; off >>= 1) {
        d1 += __shfl_down_sync(0xffffffffu, d1, off);
        d2 += __shfl_down_sync(0xffffffffu, d2, off);
    }
    if (lane == 0) { sred[wid] = d1; sred2[wid] = d2; }
    __syncthreads();
    if (tid == 0) {
        double t1 = 0.0, t2 = 0.0;
#pragma unroll
        for (int w = 0; w < 8; w++) { t1 += sred[w]; t2 += sred2[w]; }
        atomicAdd(&g_red[2 * ob], t1);
        atomicAdd(&g_red[2 * ob + 1], t2);
    }
}

// ============================================================================
// ctx: CTX[ob][n][i] = sum_j V[kvb(j)][n][jc] * attn[ob][i][j]
// CTA tile 128(n) x 128(i), grid (4, 16, 16), block 256, 2 CTAs/SM
// Direct-fragment fp16 epilogue (half2 stores, true scale). [R14 proven form]
// ============================================================================
__global__ void __launch_bounds__(256, 2) ctx_mma() {
    extern __shared__ char dsm[];
    uint32_t sb = smem_u32(dsm);

    int ob = blockIdx.z;
    int kvbase = (ob < 8) ? 8 : 0;
    int i0 = blockIdx.x << 7;
    int n0 = blockIdx.y << 7;

    int tid = threadIdx.x;
    int wid = tid >> 5, lane = tid & 31;
    int g = lane >> 2, tg = lane & 3;
    int wm = (wid & 1) * 64, wn = (wid >> 1) * 32;

    uint32_t baseA[4], baseB[2];
    uint32_t lrow = lane & 15, lcol = (lane >> 4) * 16;
#pragma unroll
    for (int mt = 0; mt < 4; mt++) baseA[mt] = swz((wm + mt * 16 + lrow) * 128 + lcol);
#pragma unroll
    for (int np = 0; np < 2; np++) baseB[np] = swz((wn + np * 16 + lrow) * 128 + lcol);

    const char* BB = (const char*)g_A + ((size_t)ob * CH + i0) * JD * 2;

    float acc[4][4][4];
#pragma unroll
    for (int a = 0; a < 4; a++)
#pragma unroll
        for (int b = 0; b < 4; b++)
#pragma unroll
            for (int c = 0; c < 4; c++) acc[a][b][c] = 0.f;

    const int NCH = JD / 64;   // 64

    auto load_chunk = [&](int c, int stg) {
        uint32_t s = sb + stg * STAGE_BYTES;
        int j0c = c * 64;
        int kvb = kvbase + (j0c >> 9);
        int jc0 = j0c & 511;
        const char* Ap = (const char*)g_V + (((size_t)kvb * NSEQ + n0) * CH + jc0) * 2;
        ldtile<128>(s,         Ap, CH * 2, tid);
        ldtile<128>(s + 16384, BB + (size_t)j0c * 2, JD * 2, tid);
        cp_commit();
    };

    load_chunk(0, 0);
    load_chunk(1, 1);
    for (int c = 0; c < NCH; c++) {
        if (c + 1 < NCH) cp_wait_group<1>(); else cp_wait_group<0>();
        __syncthreads();
        if (c + 2 < NCH) load_chunk(c + 2, (c + 2) % NSTG);
        uint32_t s = sb + (c % NSTG) * STAGE_BYTES;
        compute_stage(s, s + 16384, baseA, baseB, acc);
    }

    const float ds = 1.0f / SCALE_F;   // undo V pre-scale
    __half* gout = g_CTXh + (size_t)ob * NSEQ * CH;
#pragma unroll
    for (int mt = 0; mt < 4; mt++) {
#pragma unroll
        for (int nt = 0; nt < 4; nt++) {
            int row = n0 + wm + mt * 16 + g;
            int col = i0 + wn + nt * 8 + tg * 2;
            *(__half2*)&gout[(size_t)row * CH + col] =
                __floats2half2_rn(acc[mt][nt][0] * ds, acc[mt][nt][1] * ds);
            *(__half2*)&gout[(size_t)(row + 8) * CH + col] =
                __floats2half2_rn(acc[mt][nt][2] * ds, acc[mt][nt][3] * ds);
        }
    }
}

// ============================================================================
// fused prep: blocks [0,2048) emb->fp16; [2048,2432) W q/k/v split x256;
// [2432,2560) Wo^T fp16. Block 0 also zeroes g_red.
// ============================================================================
__global__ void __launch_bounds__(256) prep_all(const float* __restrict__ emb,
                                                const float* __restrict__ Wq,
                                                const float* __restrict__ Wk,
                                                const float* __restrict__ Wv,
                                                const float* __restrict__ Wo) {
    int bx = blockIdx.x;
    int tid = threadIdx.x;
    if (bx < 2048) {
        if (bx == 0 && tid < BTOT * 2) g_red[tid] = 0.0;
        size_t idx = ((size_t)bx * 256 + tid) * 4;
        float4 v = *(const float4*)&emb[idx];
        union { __half h[4]; uint2 u; } p;
        p.h[0] = __float2half(v.x); p.h[1] = __float2half(v.y);
        p.h[2] = __float2half(v.z); p.h[3] = __float2half(v.w);
        *(uint2*)&g_embh[idx] = p.u;
    } else if (bx < 2432) {
        int r = bx - 2048;
        int w = r >> 7;                       // 0..2
        int idx = (r & 127) * 256 + tid;      // 0..32767
        const float* src = (w == 0) ? Wq : (w == 1) ? Wk : Wv;
        int n = idx >> 6, k = idx & 63;
        float v = src[(size_t)k * CH + n] * SCALE_F;
        __half h = __float2half(v);
        __half l = __float2half(v - __half2float(h));
        size_t base = (size_t)(2 * w) * CH * CDIM;
        g_Ws[base + (size_t)n * CDIM + k] = h;
        g_Ws[base + CH * CDIM + (size_t)n * CDIM + k] = l;
    } else {
        int idx = (bx - 2432) * 256 + tid;    // 0..32767
        int k = idx >> 6, n = idx & 63;
        g_Wot[n * CH + k] = __float2half(Wo[(size_t)k * CDIM + n]);
    }
}

// ============================================================================
// QKV via tensor cores: Qt/Kt/V = embh @ Wsplit (x256).
// CTA tile 128(m) x 64(n), 8 warps 32x32, grid (CH/64=8, ROWS_TOT/128=256).
// ============================================================================
__global__ void __launch_bounds__(256) qkv_mma() {
    extern __shared__ char dsm[];
    uint32_t sb = smem_u32(dsm);
    uint32_t sEmb = sb;

    int bn = blockIdx.x << 6;
    int bm = blockIdx.y << 7;
    int tid = threadIdx.x;
    int wid = tid >> 5, lane = tid & 31;
    int g = lane >> 2, tg = lane & 3;
    int wm = (wid & 3) * 32, wn = (wid >> 2) * 32;

    uint32_t baseA[2], baseB[2];
    uint32_t lrow = lane & 15, lcol = (lane >> 4) * 16;
#pragma unroll
    for (int mt = 0; mt < 2; mt++) baseA[mt] = swz((wm + mt * 16 + lrow) * 128 + lcol);
#pragma unroll
    for (int np = 0; np < 2; np++) baseB[np] = swz((wn + np * 16 + lrow) * 128 + lcol);

    ldtile<128>(sEmb, (const char*)g_embh + (size_t)bm * CDIM * 2, CDIM * 2, tid);
#pragma unroll
    for (int w6 = 0; w6 < 6; w6++) {
        const char* wp = (const char*)g_Ws + ((size_t)w6 * CH + bn) * CDIM * 2;
        ldtile<64>(sb + 16384 + w6 * 8192, wp, CDIM * 2, tid);
    }
    cp_commit();
    cp_wait_group<0>();
    __syncthreads();

    float acc[3][2][4][4];
#pragma unroll
    for (int w = 0; w < 3; w++)
#pragma unroll
        for (int a = 0; a < 2; a++)
#pragma unroll
            for (int b = 0; b < 4; b++)
#pragma unroll
                for (int c = 0; c < 4; c++) acc[w][a][b][c] = 0.f;

#pragma unroll
    for (int kk = 0; kk < 4; kk++) {
        uint32_t kb = kk * 32;
        uint32_t ah[2][4];
#pragma unroll
        for (int mt = 0; mt < 2; mt++)
            ldsm4(ah[mt], sEmb + (baseA[mt] ^ kb));
#pragma unroll
        for (int w = 0; w < 3; w++) {
            uint32_t sH = sb + 16384 + (2 * w) * 8192;
            uint32_t sL = sH + 8192;
            uint32_t bh[2][4], bl[2][4];
#pragma unroll
            for (int np = 0; np < 2; np++) {
                ldsm4(bh[np], sH + (baseB[np] ^ kb));
                ldsm4(bl[np], sL + (baseB[np] ^ kb));
            }
#pragma unroll
            for (int np = 0; np < 2; np++) {
#pragma unroll
                for (int h = 0; h < 2; h++) {
                    int nt = np * 2 + h;
#pragma unroll
                    for (int mt = 0; mt < 2; mt++) {
                        mma16816h(acc[w][mt][nt], ah[mt], bh[np][h], bh[np][2 + h]);
                        mma16816h(acc[w][mt][nt], ah[mt], bl[np][h], bl[np][2 + h]);
                    }
                }
            }
        }
    }

    // V direct (row-major [m][c])
#pragma unroll
    for (int mt = 0; mt < 2; mt++) {
#pragma unroll
        for (int nt = 0; nt < 4; nt++) {
            int row = bm + wm + mt * 16 + g;
            int col = bn + wn + nt * 8 + tg * 2;
            *(__half2*)&g_V[(size_t)row * CH + col] =
                __floats2half2_rn(acc[2][mt][nt][0], acc[2][mt][nt][1]);
            *(__half2*)&g_V[(size_t)(row + 8) * CH + col] =
                __floats2half2_rn(acc[2][mt][nt][2], acc[2][mt][nt][3]);
        }
    }

    // Qt / Kt transposed via smem stage (pitch 136 halves)
    __half* stT = (__half*)dsm;
    int b = bm >> 11;
    int nloc = bm & 2047;
#pragma unroll
    for (int w = 0; w < 2; w++) {
        __syncthreads();
#pragma unroll
        for (int mt = 0; mt < 2; mt++) {
#pragma unroll
            for (int nt = 0; nt < 4; nt++) {
                int m = wm + mt * 16 + g;
                int col = wn + nt * 8 + tg * 2;
                stT[(col + 0) * 136 + m]     = __float2half(acc[w][mt][nt][0]);
                stT[(col + 1) * 136 + m]     = __float2half(acc[w][mt][nt][1]);
                stT[(col + 0) * 136 + m + 8] = __float2half(acc[w][mt][nt][2]);
                stT[(col + 1) * 136 + m + 8] = __float2half(acc[w][mt][nt][3]);
            }
        }
        __syncthreads();
        __half* dst = ((w == 0) ? g_Qt : g_Kt) +
                      (size_t)b * CH * NSEQ + (size_t)bn * NSEQ + nloc;
#pragma unroll
        for (int k = 0; k < 4; k++) {
            int idx = tid + k * 256;
            int row = idx >> 4, c8 = (idx & 15) * 8;
            *(uint4*)&dst[(size_t)row * NSEQ + c8] = *(uint4*)&stT[row * 136 + c8];
        }
    }
}

// ============================================================================
// out projection via tensor cores: OUT[M,64] = CTXh[M,512] @ Wot^T
// ============================================================================
__global__ void __launch_bounds__(256, 2) gemm_out_mma(float* __restrict__ Cm) {
    extern __shared__ char dsm[];
    uint32_t sb = smem_u32(dsm);

    int bm = blockIdx.x << 7;
    int tid = threadIdx.x;
    int wid = tid >> 5, lane = tid & 31;
    int g = lane >> 2, tg = lane & 3;
    int wm = (wid & 3) * 32, wn = (wid >> 2) * 32;

    uint32_t baseA[2], baseB[2];
    uint32_t lrow = lane & 15, lcol = (lane >> 4) * 16;
#pragma unroll
    for (int mt = 0; mt < 2; mt++) baseA[mt] = swz((wm + mt * 16 + lrow) * 128 + lcol);
#pragma unroll
    for (int np = 0; np < 2; np++) baseB[np] = swz((wn + np * 16 + lrow) * 128 + lcol);

    const char* AB = (const char*)g_CTXh + (size_t)bm * CH * 2;
    const char* BB = (const char*)g_Wot;

    float acc[2][4][4];
#pragma unroll
    for (int a = 0; a < 2; a++)
#pragma unroll
        for (int b = 0; b < 4; b++)
#pragma unroll
            for (int c = 0; c < 4; c++) acc[a][b][c] = 0.f;

    const int NCH = CH / 64;   // 8

    auto load_chunk = [&](int c, int stg) {
        uint32_t s = sb + stg * OSTAGE_BYTES;
        size_t ko = (size_t)c * 128;
        ldtile<128>(s,         AB + ko, CH * 2, tid);
        ldtile<64>(s + 16384,  BB + ko, CH * 2, tid);
        cp_commit();
    };

    load_chunk(0, 0);
    load_chunk(1, 1);
    for (int c = 0; c < NCH; c++) {
        if (c + 1 < NCH) cp_wait_group<1>(); else cp_wait_group<0>();
        __syncthreads();
        if (c + 2 < NCH) load_chunk(c + 2, (c + 2) % NSTG);
        uint32_t s = sb + (c % NSTG) * OSTAGE_BYTES;
        compute_stage2(s, s + 16384, baseA, baseB, acc);
    }

#pragma unroll
    for (int mt = 0; mt < 2; mt++) {
#pragma unroll
        for (int nt = 0; nt < 4; nt++) {
            int row = bm + wm + mt * 16 + g;
            int col = wn + nt * 8 + tg * 2;
            *(float2*)&Cm[(size_t)row * CDIM + col] =
                make_float2(acc[mt][nt][0], acc[mt][nt][1]);
            *(float2*)&Cm[(size_t)(row + 8) * CDIM + col] =
                make_float2(acc[mt][nt][2], acc[mt][nt][3]);
        }
    }
}

// ============================================================================
// softmax (fused rstd finalize): scale + softmax over j, write attn fp16.
// ============================================================================
__global__ void __launch_bounds__(256) softmax_k() {
    int row = blockIdx.x;
    int b = row >> 9;
    __shared__ float srstd;
    __shared__ float red[8];
    int t = threadIdx.x;

    if (t == 0) {
        const double SC = 65536.0;
        double n = (double)CH * (double)JD;
        double mean = g_red[2 * b] / (n * SC);
        double var  = g_red[2 * b + 1] / (n * SC * SC) - mean * mean;
        srstd = rsqrtf((float)var + EPS_F) / (float)SC;
    }

    const float* p = g_S + (size_t)row * JD;
    float4 xv[4];
#pragma unroll
    for (int u = 0; u < 4; u++)
        xv[u] = *(const float4*)&p[u * 1024 + t * 4];
    __syncthreads();
    float rstd = srstd;

    float* x = (float*)xv;
    float mx = -1e30f;
#pragma unroll
    for (int u = 0; u < 16; u++) {
        x[u] *= rstd;
        mx = fmaxf(mx, x[u]);
    }
    for (int off = 16; off > 0; off >>= 1)
        mx = fmaxf(mx, __shfl_xor_sync(0xffffffffu, mx, off));
    int lane = t & 31, wid = t >> 5;
    if (lane == 0) red[wid] = mx;
    __syncthreads();
    float gm = red[0];
#pragma unroll
    for (int w = 1; w < 8; w++) gm = fmaxf(gm, red[w]);
    __syncthreads();

    float sum = 0.f;
#pragma unroll
    for (int u = 0; u < 16; u++) {
        x[u] = __expf(x[u] - gm);
        sum += x[u];
    }
    for (int off = 16; off > 0; off >>= 1)
        sum += __shfl_xor_sync(0xffffffffu, sum, off);
    if (lane == 0) red[wid] = sum;
    __syncthreads();
    float tot = 0.f;
#pragma unroll
    for (int w = 0; w < 8; w++) tot += red[w];
    float inv = 1.0f / tot;

    __half* ah = g_A + (size_t)row * JD;
#pragma unroll
    for (int u = 0; u < 4; u++) {
        union { __half v[4]; uint2 q; } pk;
#pragma unroll
        for (int e = 0; e < 4; e++)
            pk.v[e] = __float2half(x[u * 4 + e] * inv);
        *(uint2*)&ah[u * 1024 + t * 4] = pk.q;
    }
}

// ============================================================================
// launch
// ============================================================================
extern "C" void kernel_launch(void* const* d_in, const int* in_sizes, int n_in,
                              void* d_out, int out_size) {
    const float* emb = (const float*)d_in[0];
    const float* Wq  = (const float*)d_in[1];
    const float* Wk  = (const float*)d_in[2];
    const float* Wv  = (const float*)d_in[3];
    const float* Wo  = (const float*)d_in[4];
    float* outp = (float*)d_out;

    cudaFuncSetAttribute(scores_mma, cudaFuncAttributeMaxDynamicSharedMemorySize, SMEM_DYN);
    cudaFuncSetAttribute(ctx_mma, cudaFuncAttributeMaxDynamicSharedMemorySize, SMEM_DYN);
    cudaFuncSetAttribute(gemm_out_mma, cudaFuncAttributeMaxDynamicSharedMemorySize, OSMEM_DYN);
    cudaFuncSetAttribute(qkv_mma, cudaFuncAttributeMaxDynamicSharedMemorySize, QSMEM);

    prep_all<<<2560, 256>>>(emb, Wq, Wk, Wv, Wo);

    qkv_mma<<<dim3(CH / 64, ROWS_TOT / 128), 256, QSMEM>>>();

    scores_mma<<<dim3(JD / 128, CH / 128, BTOT), 256, SMEM_DYN>>>();

    softmax_k<<<BTOT * CH, 256>>>();

    ctx_mma<<<dim3(CH / 128, NSEQ / 128, BTOT), 256, SMEM_DYN>>>();

    gemm_out_mma<<<ROWS_TOT / 128, 256, OSMEM_DYN>>>(outp);
}